// round 2
// baseline (speedup 1.0000x reference)
#include <cuda_runtime.h>
#include <cstddef>

// Problem constants
#define Bx 8
#define Cc 64
#define Nn 512
#define Tt 288
#define Kk 32

// kernel-2 tiling
#define NT 32
#define TT 8
#define CPAD 66   // padded c stride in shared (conflict-free: bank = 2t+2c)

typedef unsigned long long u64;

// Scratch for HO = relu(EM @ HF) + HF, laid out [b, c, k, t]
__device__ float g_HO[(size_t)Bx * Cc * Kk * Tt];

// ---- packed f32x2 helpers (FFMA2 is PTX-only on sm_103a) ----
__device__ __forceinline__ u64 pack2(float x, float y) {
    u64 r; asm("mov.b64 %0, {%1, %2};" : "=l"(r) : "f"(x), "f"(y)); return r;
}
__device__ __forceinline__ float2 unpack2(u64 v) {
    float2 r; asm("mov.b64 {%0, %1}, %2;" : "=f"(r.x), "=f"(r.y) : "l"(v)); return r;
}
__device__ __forceinline__ u64 ffma2(u64 a, u64 b, u64 c) {
    u64 d; asm("fma.rn.f32x2 %0, %1, %2, %3;" : "=l"(d) : "l"(a), "l"(b), "l"(c)); return d;
}

extern __shared__ float smem[];

// ============================================================================
// Kernel 1: per (b,c): HF[k,t] = sum_n HEs[n,k] * x[b,c,n,t]
//           HO[k,t] = relu( sum_j EM[k,j] * HF[j,t] ) + HF[k,t]  -> g_HO
// grid = 512 (b*C+c), block = 288 (one thread per t)
// smem: HEs (512*32 fl) + EM transposed (32*32 fl) = 69632 B
// ============================================================================
__global__ void __launch_bounds__(288) k1_hf(const float* __restrict__ x,
                                             const float* __restrict__ HEs,
                                             const float* __restrict__ em) {
    float* sHE  = smem;                 // [n][k], k contiguous
    float* sEMT = smem + Nn * Kk;       // transposed: sEMT[k][k'] = em[k'][k]
    const int tid = threadIdx.x;
    const int bc  = blockIdx.x;

    for (int i = tid; i < Nn * Kk; i += 288) sHE[i] = HEs[i];
    for (int i = tid; i < Kk * Kk; i += 288) {
        int kp = i >> 5, k = i & 31;
        sEMT[k * Kk + kp] = em[i];
    }
    __syncthreads();

    const float* xp = x + (size_t)bc * (Nn * Tt) + tid;

    u64 acc[16];
    #pragma unroll
    for (int i = 0; i < 16; i++) acc[i] = pack2(0.f, 0.f);

    #pragma unroll 4
    for (int n = 0; n < Nn; n++) {
        float xv = xp[n * Tt];                       // coalesced across t
        u64 xb = pack2(xv, xv);
        const u64* he2 = (const u64*)(sHE + n * Kk); // broadcast LDS.64
        #pragma unroll
        for (int kp = 0; kp < 16; kp++)
            acc[kp] = ffma2(he2[kp], xb, acc[kp]);
    }

    // edge_map mix: hm[k'] = sum_k EM[k',k]*HF[k]  (via EM^T, packed over k')
    u64 hm[16];
    #pragma unroll
    for (int i = 0; i < 16; i++) hm[i] = pack2(0.f, 0.f);
    #pragma unroll
    for (int k = 0; k < Kk; k++) {
        float2 a = unpack2(acc[k >> 1]);
        float hf = (k & 1) ? a.y : a.x;
        u64 hb = pack2(hf, hf);
        const u64* emr = (const u64*)(sEMT + k * Kk);
        #pragma unroll
        for (int kp = 0; kp < 16; kp++)
            hm[kp] = ffma2(emr[kp], hb, hm[kp]);
    }

    float* dst = g_HO + (size_t)bc * (Kk * Tt) + tid;
    #pragma unroll
    for (int kp = 0; kp < 16; kp++) {
        float2 m = unpack2(hm[kp]);
        float2 f = unpack2(acc[kp]);
        dst[(2 * kp)     * Tt] = fmaxf(m.x, 0.f) + f.x;   // coalesced across t
        dst[(2 * kp + 1) * Tt] = fmaxf(m.y, 0.f) + f.y;
    }
}

// ============================================================================
// Kernel 2: z[c,n,t] = relu( sum_k HEs[n,k]*HO[b,c,k,t] ) + x[b,c,n,t],
//           LayerNorm over c (thread-local: one thread owns all 64 c), write out.
// grid = (N/NT, T/TT, B), block = 256 = (NT n) x (TT t)
// smem: HO tile [k][t][c-padded] (32*8*66 fl) + HEs tile (32*33 fl) = 71808 B
// ============================================================================
__global__ void __launch_bounds__(256, 2) k2_scatter_ln(const float* __restrict__ x,
                                                        const float* __restrict__ HEs,
                                                        float* __restrict__ out) {
    float* sHO = smem;                       // [k][t][c] with c-stride CPAD
    float* sHE = smem + Kk * TT * CPAD;      // [n][k], row stride 33
    const int tid   = threadIdx.x;
    const int ntile = blockIdx.x;
    const int ttile = blockIdx.y;
    const int b     = blockIdx.z;
    const int t0 = ttile * TT;
    const int n0 = ntile * NT;

    for (int i = tid; i < NT * Kk; i += 256) {
        int n = i >> 5, k = i & 31;
        sHE[n * 33 + k] = HEs[(n0 + n) * Kk + k];
    }
    #pragma unroll
    for (int i = 0; i < 64; i++) {           // 64*256 = 64c*32k*8t elems
        int flat = i * 256 + tid;
        int t = flat & 7;
        int k = (flat >> 3) & 31;
        int c = flat >> 8;
        float v = g_HO[((size_t)(b * Cc + c) * Kk + k) * Tt + t0 + t];
        sHO[(k * TT + t) * CPAD + c] = v;
    }
    __syncthreads();

    const int t  = tid & 7;
    const int nl = tid >> 3;
    const int n  = n0 + nl;

    u64 acc[32];                              // y[c] pairs over c
    #pragma unroll
    for (int i = 0; i < 32; i++) acc[i] = pack2(0.f, 0.f);

    const float* heRow = sHE + nl * 33;
    #pragma unroll
    for (int k = 0; k < Kk; k++) {
        float he = heRow[k];
        u64 hb = pack2(he, he);
        const u64* row = (const u64*)(sHO + (k * TT + t) * CPAD);
        #pragma unroll
        for (int cp = 0; cp < 32; cp++)
            acc[cp] = ffma2(row[cp], hb, acc[cp]);
    }

    // residual + LayerNorm over c, all in-thread
    const size_t cstride = (size_t)Nn * Tt;
    const size_t base = ((size_t)b * Cc * Nn + n) * Tt + t0 + t;

    float z[64];
    float s1 = 0.f, s2 = 0.f;
    #pragma unroll
    for (int cp = 0; cp < 32; cp++) {
        float2 a = unpack2(acc[cp]);
        float zx = fmaxf(a.x, 0.f) + x[base + (size_t)(2 * cp)     * cstride];
        float zy = fmaxf(a.y, 0.f) + x[base + (size_t)(2 * cp + 1) * cstride];
        z[2 * cp]     = zx;
        z[2 * cp + 1] = zy;
        s1 += zx + zy;
        s2 += zx * zx + zy * zy;
    }
    float mu  = s1 * (1.f / 64.f);
    float var = fmaf(mu, -mu, s2 * (1.f / 64.f));
    float inv = rsqrtf(var + 1e-5f);
    #pragma unroll
    for (int c = 0; c < 64; c++)
        out[base + (size_t)c * cstride] = (z[c] - mu) * inv;
}

// ============================================================================
extern "C" void kernel_launch(void* const* d_in, const int* in_sizes, int n_in,
                              void* d_out, int out_size) {
    const float* x   = (const float*)d_in[0];
    const float* HEs = (const float*)d_in[1];
    const float* em  = (const float*)d_in[2];
    float* out = (float*)d_out;

    const int smem1 = (Nn * Kk + Kk * Kk) * 4;          // 69632
    const int smem2 = (Kk * TT * CPAD + NT * 33) * 4;   // 71808

    cudaFuncSetAttribute(k1_hf, cudaFuncAttributeMaxDynamicSharedMemorySize, smem1);
    cudaFuncSetAttribute(k2_scatter_ln, cudaFuncAttributeMaxDynamicSharedMemorySize, smem2);

    k1_hf<<<Bx * Cc, 288, smem1>>>(x, HEs, em);
    k2_scatter_ln<<<dim3(Nn / NT, Tt / TT, Bx), 256, smem2>>>(x, HEs, out);
}

// round 4
// speedup vs baseline: 1.4269x; 1.4269x over previous
#include <cuda_runtime.h>
#include <cstddef>

// Problem constants
#define Bx 8
#define Cc 64
#define Nn 512
#define Tt 288
#define Kk 32

// kernel-2 tiling
#define NT 32
#define TT 8
#define CSTR 66   // padded c stride (floats) in shared HO/y tile = 33 u64

typedef unsigned long long u64;

// Scratch for HO = relu(EM @ HF) + HF, laid out [b, c, k, t]
__device__ float g_HO[(size_t)Bx * Cc * Kk * Tt];

// ---- packed f32x2 helpers (FFMA2 is PTX-only on sm_103a) ----
__device__ __forceinline__ u64 pack2(float x, float y) {
    u64 r; asm("mov.b64 %0, {%1, %2};" : "=l"(r) : "f"(x), "f"(y)); return r;
}
__device__ __forceinline__ float2 unpack2(u64 v) {
    float2 r; asm("mov.b64 {%0, %1}, %2;" : "=f"(r.x), "=f"(r.y) : "l"(v)); return r;
}
__device__ __forceinline__ u64 ffma2(u64 a, u64 b, u64 c) {
    u64 d; asm("fma.rn.f32x2 %0, %1, %2, %3;" : "=l"(d) : "l"(a), "l"(b), "l"(c)); return d;
}

extern __shared__ float smem[];

// ============================================================================
// Kernel 1: per (b,c): HF[k,t] = sum_n HEs[n,k] * x[b,c,n,t]
//           HO[k,t] = relu( sum_j EM[k,j] * HF[j,t] ) + HF[k,t]  -> g_HO
// grid = 512 (b*C+c), block = 288 (one thread per t)
// Software-pipelined x loads (depth 16) to get MLP high enough to cover DRAM.
// ============================================================================
__global__ void __launch_bounds__(288) k1_hf(const float* __restrict__ x,
                                             const float* __restrict__ HEs,
                                             const float* __restrict__ em) {
    float* sHE  = smem;                 // [n][k], k contiguous
    float* sEMT = smem + Nn * Kk;       // transposed: sEMT[k][k'] = em[k'][k]
    const int tid = threadIdx.x;
    const int bc  = blockIdx.x;

    for (int i = tid; i < Nn * Kk; i += 288) sHE[i] = HEs[i];
    for (int i = tid; i < Kk * Kk; i += 288) {
        int kp = i >> 5, k = i & 31;
        sEMT[k * Kk + kp] = em[i];
    }
    __syncthreads();

    const float* xp = x + (size_t)bc * (Nn * Tt) + tid;

    u64 acc[16];
    #pragma unroll
    for (int i = 0; i < 16; i++) acc[i] = pack2(0.f, 0.f);

    float xv[16];
    #pragma unroll
    for (int i = 0; i < 16; i++) xv[i] = xp[i * Tt];

    #pragma unroll 1
    for (int n0 = 0; n0 < Nn; n0 += 16) {
        float xn[16];
        const bool more = (n0 + 16) < Nn;
        #pragma unroll
        for (int i = 0; i < 16; i++) xn[i] = more ? xp[(n0 + 16 + i) * Tt] : 0.f;

        #pragma unroll
        for (int i = 0; i < 16; i++) {
            u64 xb = pack2(xv[i], xv[i]);
            const u64* he2 = (const u64*)(sHE + (n0 + i) * Kk); // broadcast LDS.64
            #pragma unroll
            for (int kp = 0; kp < 16; kp++)
                acc[kp] = ffma2(he2[kp], xb, acc[kp]);
        }
        #pragma unroll
        for (int i = 0; i < 16; i++) xv[i] = xn[i];
    }

    // edge_map mix: hm[k'] = sum_k EM[k',k]*HF[k]  (via EM^T, packed over k')
    u64 hm[16];
    #pragma unroll
    for (int i = 0; i < 16; i++) hm[i] = pack2(0.f, 0.f);
    #pragma unroll
    for (int k = 0; k < Kk; k++) {
        float2 a = unpack2(acc[k >> 1]);
        float hf = (k & 1) ? a.y : a.x;
        u64 hb = pack2(hf, hf);
        const u64* emr = (const u64*)(sEMT + k * Kk);
        #pragma unroll
        for (int kp = 0; kp < 16; kp++)
            hm[kp] = ffma2(emr[kp], hb, hm[kp]);
    }

    float* dst = g_HO + (size_t)bc * (Kk * Tt) + tid;
    #pragma unroll
    for (int kp = 0; kp < 16; kp++) {
        float2 m = unpack2(hm[kp]);
        float2 f = unpack2(acc[kp]);
        dst[(2 * kp)     * Tt] = fmaxf(m.x, 0.f) + f.x;   // coalesced across t
        dst[(2 * kp + 1) * Tt] = fmaxf(m.y, 0.f) + f.y;
    }
}

// ============================================================================
// Kernel 2: y[n,t,c] = sum_k HEs[n,k]*HO[b,c,k,t];
//           z = relu(y)+x; LayerNorm over c; write out.
//
// Mainloop: warp = t, lane = c-pair. HO tile register-resident (ho[32] u64),
// HEs duplicated in smem -> broadcast LDS.64 per FFMA2 (1 wavefront each).
// y bounces through smem (reusing HO tile space); epilogue remaps threads to
// (n,t) so LN stays thread-local and x/out traffic stays sector-aligned.
//
// grid = (N/NT, T/TT, B), block = 256
// smem: HO/y tile 32*8*66 fl (67584 B) + HEdup 1024 u64 (8192 B) = 75776 B
// ============================================================================
__global__ void __launch_bounds__(256, 2) k2_scatter_ln(const float* __restrict__ x,
                                                        const float* __restrict__ HEs,
                                                        float* __restrict__ out) {
    float* sHO = smem;                              // [k][t][c] stride CSTR; reused as y [n][t][c]
    u64*   sHEd = (u64*)(smem + Kk * TT * CSTR);    // [n][k] duplicated pairs
    const int tid   = threadIdx.x;
    const int ntile = blockIdx.x;
    const int ttile = blockIdx.y;
    const int b     = blockIdx.z;
    const int t0 = ttile * TT;
    const int n0 = ntile * NT;

    // ---- stage HEs (duplicated into both u64 halves) ----
    #pragma unroll
    for (int i = 0; i < 4; i++) {
        int flat = i * 256 + tid;                   // k fast (32), n (32)
        int k = flat & 31, n = flat >> 5;
        float h = HEs[(n0 + n) * Kk + k];
        sHEd[flat] = pack2(h, h);
    }
    // ---- stage HO tile (gmem sector-aligned: t fastest) ----
    #pragma unroll
    for (int i = 0; i < 64; i++) {                  // 64c*32k*8t / 256
        int flat = i * 256 + tid;
        int t = flat & 7;
        int k = (flat >> 3) & 31;
        int c = flat >> 8;
        float v = g_HO[((size_t)(b * Cc + c) * Kk + k) * Tt + t0 + t];
        sHO[(k * TT + t) * CSTR + c] = v;
    }
    __syncthreads();

    const int warp_t = tid >> 5;                    // warp owns one t
    const int lane   = tid & 31;                    // lane owns c-pair

    // ---- HO tile -> registers (read once) ----
    const u64* hoB = (const u64*)sHO;               // u64 stride per row = CSTR/2 = 33
    u64 ho[32];
    #pragma unroll
    for (int k = 0; k < Kk; k++)
        ho[k] = hoB[(k * TT + warp_t) * (CSTR / 2) + lane];
    __syncthreads();                                // all ho reads done before y overwrites

    u64* yB = (u64*)sHO;                            // y tile [n][t][c], same layout
    #pragma unroll 1
    for (int h = 0; h < 2; h++) {                   // 16 n's per half (reg pressure)
        u64 acc[16];
        #pragma unroll
        for (int n = 0; n < 16; n++) acc[n] = pack2(0.f, 0.f);
        const u64* heRow = sHEd + (h * 16) * Kk;
        #pragma unroll
        for (int k = 0; k < Kk; k++) {
            u64 hok = ho[k];
            #pragma unroll
            for (int n = 0; n < 16; n++)
                acc[n] = ffma2(heRow[n * Kk + k], hok, acc[n]);   // broadcast LDS.64
        }
        #pragma unroll
        for (int n = 0; n < 16; n++)
            yB[((h * 16 + n) * TT + warp_t) * (CSTR / 2) + lane] = acc[n];
    }
    __syncthreads();

    // ---- epilogue: thread -> (n,t), LN thread-local over c ----
    const int t  = tid & 7;
    const int nl = tid >> 3;
    const int n  = n0 + nl;
    const size_t cstride = (size_t)Nn * Tt;
    const size_t base = ((size_t)b * Cc * Nn + n) * Tt + t0 + t;
    const u64* yRow = yB + (nl * TT + t) * (CSTR / 2);

    float z[64];
    float s1 = 0.f, s2 = 0.f;
    #pragma unroll
    for (int cp = 0; cp < 32; cp++) {
        float2 a = unpack2(yRow[cp]);
        float zx = fmaxf(a.x, 0.f) + x[base + (size_t)(2 * cp)     * cstride];
        float zy = fmaxf(a.y, 0.f) + x[base + (size_t)(2 * cp + 1) * cstride];
        z[2 * cp]     = zx;
        z[2 * cp + 1] = zy;
        s1 += zx + zy;
        s2 += zx * zx + zy * zy;
    }
    float mu  = s1 * (1.f / 64.f);
    float var = fmaf(mu, -mu, s2 * (1.f / 64.f));
    float inv = rsqrtf(var + 1e-5f);
    #pragma unroll
    for (int c = 0; c < 64; c++)
        out[base + (size_t)c * cstride] = (z[c] - mu) * inv;
}

// ============================================================================
extern "C" void kernel_launch(void* const* d_in, const int* in_sizes, int n_in,
                              void* d_out, int out_size) {
    const float* x   = (const float*)d_in[0];
    const float* HEs = (const float*)d_in[1];
    const float* em  = (const float*)d_in[2];
    float* out = (float*)d_out;

    const int smem1 = (Nn * Kk + Kk * Kk) * 4;          // 69632
    const int smem2 = Kk * TT * CSTR * 4 + NT * Kk * 8; // 67584 + 8192 = 75776

    cudaFuncSetAttribute(k1_hf, cudaFuncAttributeMaxDynamicSharedMemorySize, smem1);
    cudaFuncSetAttribute(k2_scatter_ln, cudaFuncAttributeMaxDynamicSharedMemorySize, smem2);

    k1_hf<<<Bx * Cc, 288, smem1>>>(x, HEs, em);
    k2_scatter_ln<<<dim3(Nn / NT, Tt / TT, Bx), 256, smem2>>>(x, HEs, out);
}

// round 5
// speedup vs baseline: 1.4316x; 1.0032x over previous
#include <cuda_runtime.h>
#include <cstddef>

// Problem constants
#define Bx 8
#define Cc 64
#define Nn 512
#define Tt 288
#define Kk 32

// kernel-2 tiling
#define NT 32
#define TT 8
#define CSTR 66   // padded c stride (floats) in shared HO/y tile = 33 u64

typedef unsigned long long u64;

// Scratch for HO = relu(EM @ HF) + HF, laid out [b, c, k, t]
__device__ float g_HO[(size_t)Bx * Cc * Kk * Tt];

// ---- packed f32x2 helpers (FFMA2 is PTX-only on sm_103a) ----
__device__ __forceinline__ u64 pack2(float x, float y) {
    u64 r; asm("mov.b64 %0, {%1, %2};" : "=l"(r) : "f"(x), "f"(y)); return r;
}
__device__ __forceinline__ float2 unpack2(u64 v) {
    float2 r; asm("mov.b64 {%0, %1}, %2;" : "=f"(r.x), "=f"(r.y) : "l"(v)); return r;
}
__device__ __forceinline__ u64 ffma2(u64 a, u64 b, u64 c) {
    u64 d; asm("fma.rn.f32x2 %0, %1, %2, %3;" : "=l"(d) : "l"(a), "l"(b), "l"(c)); return d;
}

extern __shared__ float smem[];

// ============================================================================
// Kernel 1: per (b,c): HF[k,t] = sum_n HEs[n,k] * x[b,c,n,t]
//           HO[k,t] = relu( sum_j EM[k,j] * HF[j,t] ) + HF[k,t]  -> g_HO
// grid = 512 (b*C+c), block = 288 (one thread per t)
// Software-pipelined x loads (depth 16); HE fetched as broadcast LDS.128
// (one wavefront feeding TWO FFMA2) to stay under the smem crossbar limit.
// ============================================================================
__global__ void __launch_bounds__(288) k1_hf(const float* __restrict__ x,
                                             const float* __restrict__ HEs,
                                             const float* __restrict__ em) {
    float* sHE  = smem;                 // [n][k], k contiguous
    float* sEMT = smem + Nn * Kk;       // transposed: sEMT[k][k'] = em[k'][k]
    const int tid = threadIdx.x;
    const int bc  = blockIdx.x;

    for (int i = tid; i < Nn * Kk; i += 288) sHE[i] = HEs[i];
    for (int i = tid; i < Kk * Kk; i += 288) {
        int kp = i >> 5, k = i & 31;
        sEMT[k * Kk + kp] = em[i];
    }
    __syncthreads();

    const float* xp = x + (size_t)bc * (Nn * Tt) + tid;

    u64 acc[16];
    #pragma unroll
    for (int i = 0; i < 16; i++) acc[i] = pack2(0.f, 0.f);

    float xv[16];
    #pragma unroll
    for (int i = 0; i < 16; i++) xv[i] = xp[i * Tt];

    #pragma unroll 1
    for (int n0 = 0; n0 < Nn; n0 += 16) {
        float xn[16];
        const bool more = (n0 + 16) < Nn;
        #pragma unroll
        for (int i = 0; i < 16; i++) xn[i] = more ? xp[(n0 + 16 + i) * Tt] : 0.f;

        #pragma unroll
        for (int i = 0; i < 16; i++) {
            u64 xb = pack2(xv[i], xv[i]);
            const ulonglong2* he4 = (const ulonglong2*)(sHE + (n0 + i) * Kk);
            #pragma unroll
            for (int q = 0; q < 8; q++) {            // broadcast LDS.128
                ulonglong2 hh = he4[q];
                acc[2 * q]     = ffma2(hh.x, xb, acc[2 * q]);
                acc[2 * q + 1] = ffma2(hh.y, xb, acc[2 * q + 1]);
            }
        }
        #pragma unroll
        for (int i = 0; i < 16; i++) xv[i] = xn[i];
    }

    // edge_map mix: hm[k'] = sum_k EM[k',k]*HF[k]  (via EM^T, packed over k')
    u64 hm[16];
    #pragma unroll
    for (int i = 0; i < 16; i++) hm[i] = pack2(0.f, 0.f);
    #pragma unroll
    for (int k = 0; k < Kk; k++) {
        float2 a = unpack2(acc[k >> 1]);
        float hf = (k & 1) ? a.y : a.x;
        u64 hb = pack2(hf, hf);
        const ulonglong2* emr = (const ulonglong2*)(sEMT + k * Kk);
        #pragma unroll
        for (int q = 0; q < 8; q++) {
            ulonglong2 ee = emr[q];
            hm[2 * q]     = ffma2(ee.x, hb, hm[2 * q]);
            hm[2 * q + 1] = ffma2(ee.y, hb, hm[2 * q + 1]);
        }
    }

    float* dst = g_HO + (size_t)bc * (Kk * Tt) + tid;
    #pragma unroll
    for (int kp = 0; kp < 16; kp++) {
        float2 m = unpack2(hm[kp]);
        float2 f = unpack2(acc[kp]);
        dst[(2 * kp)     * Tt] = fmaxf(m.x, 0.f) + f.x;   // coalesced across t
        dst[(2 * kp + 1) * Tt] = fmaxf(m.y, 0.f) + f.y;
    }
}

// ============================================================================
// Kernel 2: y[n,t,c] = sum_k HEs[n,k]*HO[b,c,k,t];
//           z = relu(y)+x; LayerNorm over c; write out.
//
// Mainloop: warp = t, lane = c-pair. HO tile register-resident (ho[32] u64),
// HEs duplicated pairs in smem; fetched per k-PAIR as broadcast LDS.128 so
// each smem wavefront feeds two FFMA2. y bounces through smem; epilogue
// remaps threads to (n,t) so LN stays thread-local.
//
// grid = (N/NT, T/TT, B), block = 256
// smem: HO/y tile 32*8*66 fl (67584 B) + HEdup 1024 u64 (8192 B) = 75776 B
// ============================================================================
__global__ void __launch_bounds__(256, 2) k2_scatter_ln(const float* __restrict__ x,
                                                        const float* __restrict__ HEs,
                                                        float* __restrict__ out) {
    float* sHO = smem;                              // [k][t][c] stride CSTR; reused as y [n][t][c]
    u64*   sHEd = (u64*)(smem + Kk * TT * CSTR);    // [n][k] duplicated pairs
    const int tid   = threadIdx.x;
    const int ntile = blockIdx.x;
    const int ttile = blockIdx.y;
    const int b     = blockIdx.z;
    const int t0 = ttile * TT;
    const int n0 = ntile * NT;

    // ---- stage HEs (duplicated into both u64 halves) ----
    #pragma unroll
    for (int i = 0; i < 4; i++) {
        int flat = i * 256 + tid;                   // k fast (32), n (32)
        int k = flat & 31, n = flat >> 5;
        float h = HEs[(n0 + n) * Kk + k];
        sHEd[flat] = pack2(h, h);
    }
    // ---- stage HO tile (gmem sector-aligned: t fastest) ----
    #pragma unroll
    for (int i = 0; i < 64; i++) {                  // 64c*32k*8t / 256
        int flat = i * 256 + tid;
        int t = flat & 7;
        int k = (flat >> 3) & 31;
        int c = flat >> 8;
        float v = g_HO[((size_t)(b * Cc + c) * Kk + k) * Tt + t0 + t];
        sHO[(k * TT + t) * CSTR + c] = v;
    }
    __syncthreads();

    const int warp_t = tid >> 5;                    // warp owns one t
    const int lane   = tid & 31;                    // lane owns c-pair

    // ---- HO tile -> registers (read once) ----
    const u64* hoB = (const u64*)sHO;               // u64 stride per row = CSTR/2 = 33
    u64 ho[32];
    #pragma unroll
    for (int k = 0; k < Kk; k++)
        ho[k] = hoB[(k * TT + warp_t) * (CSTR / 2) + lane];
    __syncthreads();                                // all ho reads done before y overwrites

    u64* yB = (u64*)sHO;                            // y tile [n][t][c], same layout
    #pragma unroll 1
    for (int h = 0; h < 2; h++) {                   // 16 n's per half (reg pressure)
        u64 acc[16];
        #pragma unroll
        for (int n = 0; n < 16; n++) acc[n] = pack2(0.f, 0.f);
        const u64* heRow = sHEd + (h * 16) * Kk;
        #pragma unroll
        for (int kq = 0; kq < 16; kq++) {           // k-pairs
            u64 hok0 = ho[2 * kq];
            u64 hok1 = ho[2 * kq + 1];
            #pragma unroll
            for (int n = 0; n < 16; n++) {
                ulonglong2 hp = *(const ulonglong2*)(heRow + n * Kk + 2 * kq); // broadcast LDS.128
                acc[n] = ffma2(hp.x, hok0, acc[n]);
                acc[n] = ffma2(hp.y, hok1, acc[n]);
            }
        }
        #pragma unroll
        for (int n = 0; n < 16; n++)
            yB[((h * 16 + n) * TT + warp_t) * (CSTR / 2) + lane] = acc[n];
    }
    __syncthreads();

    // ---- epilogue: thread -> (n,t), LN thread-local over c ----
    const int t  = tid & 7;
    const int nl = tid >> 3;
    const int n  = n0 + nl;
    const size_t cstride = (size_t)Nn * Tt;
    const size_t base = ((size_t)b * Cc * Nn + n) * Tt + t0 + t;
    const u64* yRow = yB + (nl * TT + t) * (CSTR / 2);

    float z[64];
    float s1 = 0.f, s2 = 0.f;
    #pragma unroll
    for (int cp = 0; cp < 32; cp++) {
        float2 a = unpack2(yRow[cp]);
        float zx = fmaxf(a.x, 0.f) + x[base + (size_t)(2 * cp)     * cstride];
        float zy = fmaxf(a.y, 0.f) + x[base + (size_t)(2 * cp + 1) * cstride];
        z[2 * cp]     = zx;
        z[2 * cp + 1] = zy;
        s1 += zx + zy;
        s2 += zx * zx + zy * zy;
    }
    float mu  = s1 * (1.f / 64.f);
    float var = fmaf(mu, -mu, s2 * (1.f / 64.f));
    float inv = rsqrtf(var + 1e-5f);
    #pragma unroll
    for (int c = 0; c < 64; c++)
        out[base + (size_t)c * cstride] = (z[c] - mu) * inv;
}

// ============================================================================
extern "C" void kernel_launch(void* const* d_in, const int* in_sizes, int n_in,
                              void* d_out, int out_size) {
    const float* x   = (const float*)d_in[0];
    const float* HEs = (const float*)d_in[1];
    const float* em  = (const float*)d_in[2];
    float* out = (float*)d_out;

    const int smem1 = (Nn * Kk + Kk * Kk) * 4;          // 69632
    const int smem2 = Kk * TT * CSTR * 4 + NT * Kk * 8; // 67584 + 8192 = 75776

    cudaFuncSetAttribute(k1_hf, cudaFuncAttributeMaxDynamicSharedMemorySize, smem1);
    cudaFuncSetAttribute(k2_scatter_ln, cudaFuncAttributeMaxDynamicSharedMemorySize, smem2);

    k1_hf<<<Bx * Cc, 288, smem1>>>(x, HEs, em);
    k2_scatter_ln<<<dim3(Nn / NT, Tt / TT, Bx), 256, smem2>>>(x, HEs, out);
}